// round 4
// baseline (speedup 1.0000x reference)
#include <cuda_runtime.h>
#include <cuda_bf16.h>

#define BB    64      // batch
#define LL    4096    // seq len
#define DD    256     // hidden dim
#define VOCAB 33

// ---- K1 config ----
#define CHUNKS   8
#define NT1      512               // threads per K1 block = tokens per chunk
#define NWARP1   (NT1 / 32)

// ---- K2 config ----
#define NT2      1024
#define KG       16                // split-K groups
#define KPG      16                // k per group

// Cross-kernel histogram accumulator; statically zeroed, K2 re-zeroes after use.
__device__ int gcnt[BB][VOCAB];

// ===================== K1: partial histograms =====================
__global__ __launch_bounds__(NT1, 4)
void hist_kernel(const int* __restrict__ X,
                 const int* __restrict__ vlen)
{
    __shared__ int whist[NWARP1][VOCAB];

    const int row   = blockIdx.x >> 3;        // 0..63
    const int chunk = blockIdx.x & 7;         // 0..7
    const int base  = chunk * NT1;
    const int tid   = threadIdx.x;
    const int warp  = tid >> 5;

    const int vl = vlen[row];
    if (base >= vl) return;                   // whole chunk masked out

    for (int i = tid; i < NWARP1 * VOCAB; i += NT1)
        (&whist[0][0])[i] = 0;
    __syncthreads();

    const int l = base + tid;
    if (l < vl) {
        int tok = X[row * LL + l];            // coalesced 4B loads
        atomicAdd(&whist[warp][tok], 1);
    }
    __syncthreads();

    if (tid < VOCAB) {
        int s = 0;
        #pragma unroll
        for (int w = 0; w < NWARP1; w++) s += whist[w][tid];
        if (s > 0) atomicAdd(&gcnt[row][tid], s);
    }
}

// ===================== K2: pool + MLP =====================
__global__ __launch_bounds__(NT2, 1)
void mlp_kernel(const float* __restrict__ emb,
                const float* __restrict__ W1,
                const float* __restrict__ b1,
                const float* __restrict__ W2,
                const float* __restrict__ b2,
                float* __restrict__ out)
{
    __shared__ float cnt[36];                          // padded, [33..35]=0
    __shared__ alignas(16) float vecA[DD];             // pooled, then h
    __shared__ alignas(16) float part[KG][DD];         // split-K partials

    const int b   = blockIdx.x;
    const int tid = threadIdx.x;

    // ---- pull counts, zero accumulator for next graph replay ----
    if (tid < 36) {
        float s = 0.0f;
        if (tid < VOCAB) {
            s = (float)gcnt[b][tid];
            gcnt[b][tid] = 0;                          // self-cleaning
        }
        cnt[tid] = s;
    }
    __syncthreads();

    // ---- pooled[d] = sum_v cnt[v]*emb[v][d], 4-way vocab split ----
    {
        const int g4 = tid >> 8;      // 0..3
        const int d  = tid & 255;
        float acc = 0.0f;
        #pragma unroll
        for (int j = 0; j < 9; j++) {
            const int v = g4 * 9 + j; // 0..35
            if (v < VOCAB)
                acc = fmaf(cnt[v], emb[v * DD + d], acc);
        }
        part[g4][d] = acc;
    }
    __syncthreads();
    if (tid < DD)
        vecA[tid] = part[0][tid] + part[1][tid] + part[2][tid] + part[3][tid];
    __syncthreads();

    const int g    = tid >> 6;   // split-K group: 0..15
    const int lane = tid & 63;   // output float4 index
    const int k0   = g * KPG;

    // ---- layer 1: h = relu(pooled @ W1 + b1) ----
    {
        const float4* W1v = (const float4*)W1;
        float4 acc = make_float4(0.f, 0.f, 0.f, 0.f);
        #pragma unroll
        for (int kk = 0; kk < KPG; kk++) {
            const int k = k0 + kk;
            const float  s = vecA[k];
            const float4 w = W1v[k * (DD / 4) + lane];
            acc.x = fmaf(s, w.x, acc.x);
            acc.y = fmaf(s, w.y, acc.y);
            acc.z = fmaf(s, w.z, acc.z);
            acc.w = fmaf(s, w.w, acc.w);
        }
        ((float4*)part[g])[lane] = acc;
        __syncthreads();

        if (tid < DD) {
            float h = b1[tid];
            #pragma unroll
            for (int r = 0; r < KG; r++) h += part[r][tid];
            vecA[tid] = fmaxf(h, 0.0f);
        }
        __syncthreads();
    }

    // ---- layer 2: out = relu(h @ W2 + b2) ----
    {
        const float4* W2v = (const float4*)W2;
        float4 acc = make_float4(0.f, 0.f, 0.f, 0.f);
        #pragma unroll
        for (int kk = 0; kk < KPG; kk++) {
            const int k = k0 + kk;
            const float  s = vecA[k];
            const float4 w = W2v[k * (DD / 4) + lane];
            acc.x = fmaf(s, w.x, acc.x);
            acc.y = fmaf(s, w.y, acc.y);
            acc.z = fmaf(s, w.z, acc.z);
            acc.w = fmaf(s, w.w, acc.w);
        }
        ((float4*)part[g])[lane] = acc;
        __syncthreads();

        if (tid < DD) {
            float o = b2[tid];
            #pragma unroll
            for (int r = 0; r < KG; r++) o += part[r][tid];
            out[b * DD + tid] = fmaxf(o, 0.0f);
        }
    }
}

extern "C" void kernel_launch(void* const* d_in, const int* in_sizes, int n_in,
                              void* d_out, int out_size)
{
    const int*   X    = (const int*)d_in[0];
    const int*   vlen = (const int*)d_in[1];
    const float* emb  = (const float*)d_in[2];
    const float* W1   = (const float*)d_in[3];
    const float* b1   = (const float*)d_in[4];
    const float* W2   = (const float*)d_in[5];
    const float* b2   = (const float*)d_in[6];
    float*       out  = (float*)d_out;

    hist_kernel<<<BB * CHUNKS, NT1>>>(X, vlen);
    mlp_kernel<<<BB, NT2>>>(emb, W1, b1, W2, b2, out);
}